// round 4
// baseline (speedup 1.0000x reference)
#include <cuda_runtime.h>
#include <mma.h>
#include <math.h>

using namespace nvcuda;

#define T_STEPS 1024
#define BATCH   256
#define E_DIM   128
#define G4      512

// 512 MB scratch for x_proj[t][b][g]
__device__ float g_xproj[134217728];

// ---------------------------------------------------------------------------
// Kernel 1: x_proj = x @ W_ih^T + (b_ih + b_hh), tf32 tensor cores (wmma).
// ---------------------------------------------------------------------------
__global__ __launch_bounds__(256, 2)
void xproj_gemm_tf32(const float* __restrict__ A,
                     const float* __restrict__ W,
                     const float* __restrict__ bih,
                     const float* __restrict__ bhh)
{
    constexpr int AP = 36;
    __shared__ float As[128 * AP];
    __shared__ float Bs[128 * AP];
    __shared__ float BiasT[16 * 132];

    const int n0  = blockIdx.x * 128;
    const int m0  = blockIdx.y * 128;
    const int tid = threadIdx.x;
    const int warp = tid >> 5;
    const int wm = (warp >> 2) * 64;
    const int wn = (warp & 3) * 32;

    for (int i = tid; i < 16 * 128; i += 256) {
        int r = i >> 7, c = i & 127;
        BiasT[r * 132 + c] = bih[n0 + c] + bhh[n0 + c];
    }
    __syncthreads();

    wmma::fragment<wmma::accumulator, 16, 16, 8, float> cf[4][2];
#pragma unroll
    for (int i = 0; i < 4; i++)
#pragma unroll
        for (int j = 0; j < 2; j++)
            wmma::load_matrix_sync(cf[i][j], &BiasT[wn + j * 16], 132, wmma::mem_row_major);
    __syncthreads();

    for (int kt = 0; kt < 256; kt += 32) {
#pragma unroll
        for (int l = 0; l < 4; l++) {
            int i   = tid + l * 256;
            int row = i >> 3;
            int kq  = (i & 7) * 4;
            float4 av = *reinterpret_cast<const float4*>(&A[(size_t)(m0 + row) * 256 + kt + kq]);
            *reinterpret_cast<float4*>(&As[row * AP + kq]) = av;
            float4 bv = *reinterpret_cast<const float4*>(&W[(size_t)(n0 + row) * 256 + kt + kq]);
            *reinterpret_cast<float4*>(&Bs[row * AP + kq]) = bv;
        }
        __syncthreads();

#pragma unroll
        for (int kk = 0; kk < 32; kk += 8) {
            wmma::fragment<wmma::matrix_a, 16, 16, 8, wmma::precision::tf32, wmma::row_major> af[4];
            wmma::fragment<wmma::matrix_b, 16, 16, 8, wmma::precision::tf32, wmma::col_major> bf[2];
#pragma unroll
            for (int i = 0; i < 4; i++) {
                wmma::load_matrix_sync(af[i], &As[(wm + i * 16) * AP + kk], AP);
#pragma unroll
                for (int t = 0; t < af[i].num_elements; t++)
                    af[i].x[t] = wmma::__float_to_tf32(af[i].x[t]);
            }
#pragma unroll
            for (int j = 0; j < 2; j++) {
                wmma::load_matrix_sync(bf[j], &Bs[(wn + j * 16) * AP + kk], AP);
#pragma unroll
                for (int t = 0; t < bf[j].num_elements; t++)
                    bf[j].x[t] = wmma::__float_to_tf32(bf[j].x[t]);
            }
#pragma unroll
            for (int i = 0; i < 4; i++)
#pragma unroll
                for (int j = 0; j < 2; j++)
                    wmma::mma_sync(cf[i][j], af[i], bf[j], cf[i][j]);
        }
        __syncthreads();
    }

#pragma unroll
    for (int i = 0; i < 4; i++)
#pragma unroll
        for (int j = 0; j < 2; j++) {
            float* dst = &g_xproj[(size_t)(m0 + wm + i * 16) * 512 + n0 + wn + j * 16];
            wmma::store_matrix_sync(dst, cf[i][j], 512, wmma::mem_row_major);
        }
}

// ---------------------------------------------------------------------------
// Kernel 2: persistent LSTM recurrence, k-pair-packed fp32x2 (no dup movs).
// 128 CTAs x 512 threads, 2 batches/CTA.
// Thread t: kh = t>>8 (k-half), tt = t&255, gates ga=tt, gb=tt+256.
// Per (gate, half): 24 k from shared (natural pairs), 40 k in registers
// (native u64 pairs). 4 accumulators {ga,gb}x{b0,b1}, packed over even/odd k,
// horizontal-added, combined via partial buffer in smem.
// ---------------------------------------------------------------------------
#define SH_CH 6    // shared 4-k chunks per half (24 k)
#define RG_CH 10   // register 4-k chunks per half (40 k)
#define RG_PAIRS 20

typedef unsigned long long u64;

__device__ __forceinline__ void fma2(u64& d, u64 a, u64 b) {
    asm("fma.rn.f32x2 %0, %1, %2, %0;" : "+l"(d) : "l"(a), "l"(b));
}
__device__ __forceinline__ float hsum2(u64 v) {
    float lo, hi;
    asm("mov.b64 {%0, %1}, %2;" : "=f"(lo), "=f"(hi) : "l"(v));
    return lo + hi;
}
__device__ __forceinline__ float fast_sigmoid(float x) {
    return __fdividef(1.f, 1.f + __expf(-x));
}
__device__ __forceinline__ float fast_tanh(float x) {
    float e = __expf(2.f * x);
    return 1.f - __fdividef(2.f, e + 1.f);
}

// smem layout (floats):
//   Wsh   : [2][SH_CH][512] float4   -> 2*6*512*4 = 24576 floats
//   hshf  : [2][128]                 -> 256 floats   (offset 24576)
//   partf : [2][512][2]              -> 2048 floats  (offset 24832)
#define SMEM_W_F4   (2 * SH_CH * 512)
#define SMEM_H_OFF  (SMEM_W_F4 * 4)
#define SMEM_P_OFF  (SMEM_H_OFF + 256)
#define SMEM_FLOATS (SMEM_P_OFF + 2048)

__global__ __launch_bounds__(512, 1)
void lstm_rec(const float* __restrict__ Whh,
              const float* __restrict__ h0,
              const float* __restrict__ c0,
              float* __restrict__ out)
{
    extern __shared__ float smem[];
    float* hshf  = smem + SMEM_H_OFF;
    float* partf = smem + SMEM_P_OFF;

    const int t   = threadIdx.x;
    const int blk = blockIdx.x;
    const int kh  = t >> 8;        // 0 or 1
    const int tt  = t & 255;
    const int ga  = tt;
    const int gb  = tt + 256;
    const int kbase = kh * 64;

    // --- cooperative load of shared weight chunks ---
    // smem float i = ((kc)*512 + g)*4 + j  <->  Whh[g*128 + (kc>=SH_CH? 64:0) + (kc%SH_CH)*4 + j]
    for (int i = t; i < SMEM_W_F4 * 4; i += 512) {
        int j  = i & 3;
        int g  = (i >> 2) & 511;
        int kc = i >> 11;                 // 0..11 = kh*SH_CH + c
        int khh = kc / SH_CH, c = kc % SH_CH;
        smem[i] = Whh[g * 128 + khh * 64 + c * 4 + j];
    }

    // --- register weights: k in [kbase+24, kbase+64) as native u64 pairs ---
    u64 wA[RG_PAIRS], wB[RG_PAIRS];
    {
        const u64* pa = reinterpret_cast<const u64*>(Whh + ga * 128 + kbase + SH_CH * 4);
        const u64* pb = reinterpret_cast<const u64*>(Whh + gb * 128 + kbase + SH_CH * 4);
#pragma unroll
        for (int i = 0; i < RG_PAIRS; i++) { wA[i] = pa[i]; wB[i] = pb[i]; }
    }

    // --- state init (t<256 threads own (b,e)) ---
    const int b  = tt >> 7;
    const int e  = tt & 127;
    const int bg = blk * 2 + b;
    float creg = 0.f;
    if (kh == 0) {
        hshf[b * 128 + e] = h0[bg * 128 + e];
        creg = c0[bg * 128 + e];
    }
    __syncthreads();

    const float* xp0 = g_xproj + (size_t)(blk * 2) * 512;       // batch0
    const float* xp1 = g_xproj + (size_t)(blk * 2 + 1) * 512;   // batch1
    float* outp = out + (size_t)bg * E_DIM + e;                  // for both kh roles

    const ulonglong2* Wsh2 = reinterpret_cast<const ulonglong2*>(smem);
    const ulonglong2* Hb0  = reinterpret_cast<const ulonglong2*>(hshf + kbase);
    const ulonglong2* Hb1  = reinterpret_cast<const ulonglong2*>(hshf + 128 + kbase);

    // xp prefetch (kh==0 threads only)
    float xA0 = 0.f, xA1 = 0.f, xB0 = 0.f, xB1 = 0.f;
    if (kh == 0) {
        xA0 = xp0[ga]; xA1 = xp1[ga];
        xB0 = xp0[gb]; xB1 = xp1[gb];
    }

    float* pA = partf + (kh * 512 + ga) * 2;
    float* pB = partf + (kh * 512 + gb) * 2;

    for (int step = 0; step < T_STEPS; step++) {
        // deferred softplus + output store for previous step (kh==1 warps),
        // overlapped with this step's FMA phase. hshf holds h_{step-1} here.
        if (kh == 1 && step > 0) {
            float h = hshf[b * 128 + e];
            outp[(size_t)(step - 1) * (BATCH * E_DIM)] = log1pf(__expf(h));
        }

        // prefetch next xp (kh==0)
        float nA0 = 0.f, nA1 = 0.f, nB0 = 0.f, nB1 = 0.f;
        if (kh == 0) {
            int ns = (step + 1 < T_STEPS) ? step + 1 : step;
            size_t soff = (size_t)ns * (BATCH * G4);
            nA0 = __ldg(&xp0[soff + ga]); nA1 = __ldg(&xp1[soff + ga]);
            nB0 = __ldg(&xp0[soff + gb]); nB1 = __ldg(&xp1[soff + gb]);
        }

        u64 aA0 = 0, aA1 = 0, aB0 = 0, aB1 = 0;

        // shared-weight chunks (k = kbase .. kbase+23)
#pragma unroll
        for (int c = 0; c < SH_CH; c++) {
            ulonglong2 wa = Wsh2[(kh * SH_CH + c) * 512 + ga];
            ulonglong2 wb = Wsh2[(kh * SH_CH + c) * 512 + gb];
            ulonglong2 h0c = Hb0[c];
            ulonglong2 h1c = Hb1[c];
            fma2(aA0, wa.x, h0c.x); fma2(aA0, wa.y, h0c.y);
            fma2(aA1, wa.x, h1c.x); fma2(aA1, wa.y, h1c.y);
            fma2(aB0, wb.x, h0c.x); fma2(aB0, wb.y, h0c.y);
            fma2(aB1, wb.x, h1c.x); fma2(aB1, wb.y, h1c.y);
        }
        // register-weight chunks (k = kbase+24 .. kbase+63)
#pragma unroll
        for (int c = 0; c < RG_CH; c++) {
            ulonglong2 h0c = Hb0[SH_CH + c];
            ulonglong2 h1c = Hb1[SH_CH + c];
            u64 wa0 = wA[2 * c], wa1 = wA[2 * c + 1];
            u64 wb0 = wB[2 * c], wb1 = wB[2 * c + 1];
            fma2(aA0, wa0, h0c.x); fma2(aA0, wa1, h0c.y);
            fma2(aA1, wa0, h1c.x); fma2(aA1, wa1, h1c.y);
            fma2(aB0, wb0, h0c.x); fma2(aB0, wb1, h0c.y);
            fma2(aB1, wb0, h1c.x); fma2(aB1, wb1, h1c.y);
        }

        // horizontal sums + xp add (kh==0 carries the xp term)
        float sA0 = hsum2(aA0) + xA0;
        float sA1 = hsum2(aA1) + xA1;
        float sB0 = hsum2(aB0) + xB0;
        float sB1 = hsum2(aB1) + xB1;
        pA[0] = sA0; pA[1] = sA1;
        pB[0] = sB0; pB[1] = sB1;
        __syncthreads();

        // epilogue: t < 256, thread (b, e)
        if (kh == 0) {
            float gi = partf[(0   + e) * 2 + b] + partf[(512 + 0   + e) * 2 + b];
            float gf = partf[(128 + e) * 2 + b] + partf[(512 + 128 + e) * 2 + b];
            float gg = partf[(256 + e) * 2 + b] + partf[(512 + 256 + e) * 2 + b];
            float go = partf[(384 + e) * 2 + b] + partf[(512 + 384 + e) * 2 + b];
            float i_ = fast_sigmoid(gi);
            float f_ = fast_sigmoid(gf);
            float g_ = fast_tanh(gg);
            float o_ = fast_sigmoid(go);
            creg = f_ * creg + i_ * g_;
            float h = o_ * fast_tanh(creg);
            hshf[b * 128 + e] = h;
        }
        __syncthreads();

        xA0 = nA0; xA1 = nA1; xB0 = nB0; xB1 = nB1;
    }

    // final step's output (kh==1 threads)
    if (kh == 1) {
        float h = hshf[b * 128 + e];
        outp[(size_t)(T_STEPS - 1) * (BATCH * E_DIM)] = log1pf(__expf(h));
    }
}

// ---------------------------------------------------------------------------
extern "C" void kernel_launch(void* const* d_in, const int* in_sizes, int n_in,
                              void* d_out, int out_size)
{
    const float* x   = (const float*)d_in[0];
    const float* h0  = (const float*)d_in[1];
    const float* c0  = (const float*)d_in[2];
    const float* Wih = (const float*)d_in[3];
    const float* Whh = (const float*)d_in[4];
    const float* bih = (const float*)d_in[5];
    const float* bhh = (const float*)d_in[6];
    float* out = (float*)d_out;

    const int smem_bytes = SMEM_FLOATS * 4;  // 107,520 B
    cudaFuncSetAttribute((const void*)lstm_rec,
                         cudaFuncAttributeMaxDynamicSharedMemorySize, smem_bytes);

    xproj_gemm_tf32<<<dim3(4, 2048), 256>>>(x, Wih, bih, bhh);
    lstm_rec<<<128, 512, smem_bytes>>>(Whh, h0, c0, out);
}

// round 5
// speedup vs baseline: 1.0003x; 1.0003x over previous
#include <cuda_runtime.h>
#include <mma.h>
#include <math.h>

using namespace nvcuda;

#define T_STEPS 1024
#define BATCH   256
#define E_DIM   128
#define G4      512

// 512 MB scratch for x_proj[t][b][g]
__device__ float g_xproj[134217728];

// ---------------------------------------------------------------------------
// Kernel 1: x_proj = x @ W_ih^T + (b_ih + b_hh), tf32 tensor cores (wmma).
// ---------------------------------------------------------------------------
__global__ __launch_bounds__(256, 2)
void xproj_gemm_tf32(const float* __restrict__ A,
                     const float* __restrict__ W,
                     const float* __restrict__ bih,
                     const float* __restrict__ bhh)
{
    constexpr int AP = 36;
    __shared__ float As[128 * AP];
    __shared__ float Bs[128 * AP];
    __shared__ float BiasT[16 * 132];

    const int n0  = blockIdx.x * 128;
    const int m0  = blockIdx.y * 128;
    const int tid = threadIdx.x;
    const int warp = tid >> 5;
    const int wm = (warp >> 2) * 64;
    const int wn = (warp & 3) * 32;

    for (int i = tid; i < 16 * 128; i += 256) {
        int r = i >> 7, c = i & 127;
        BiasT[r * 132 + c] = bih[n0 + c] + bhh[n0 + c];
    }
    __syncthreads();

    wmma::fragment<wmma::accumulator, 16, 16, 8, float> cf[4][2];
#pragma unroll
    for (int i = 0; i < 4; i++)
#pragma unroll
        for (int j = 0; j < 2; j++)
            wmma::load_matrix_sync(cf[i][j], &BiasT[wn + j * 16], 132, wmma::mem_row_major);
    __syncthreads();

    for (int kt = 0; kt < 256; kt += 32) {
#pragma unroll
        for (int l = 0; l < 4; l++) {
            int i   = tid + l * 256;
            int row = i >> 3;
            int kq  = (i & 7) * 4;
            float4 av = *reinterpret_cast<const float4*>(&A[(size_t)(m0 + row) * 256 + kt + kq]);
            *reinterpret_cast<float4*>(&As[row * AP + kq]) = av;
            float4 bv = *reinterpret_cast<const float4*>(&W[(size_t)(n0 + row) * 256 + kt + kq]);
            *reinterpret_cast<float4*>(&Bs[row * AP + kq]) = bv;
        }
        __syncthreads();

#pragma unroll
        for (int kk = 0; kk < 32; kk += 8) {
            wmma::fragment<wmma::matrix_a, 16, 16, 8, wmma::precision::tf32, wmma::row_major> af[4];
            wmma::fragment<wmma::matrix_b, 16, 16, 8, wmma::precision::tf32, wmma::col_major> bf[2];
#pragma unroll
            for (int i = 0; i < 4; i++) {
                wmma::load_matrix_sync(af[i], &As[(wm + i * 16) * AP + kk], AP);
#pragma unroll
                for (int t = 0; t < af[i].num_elements; t++)
                    af[i].x[t] = wmma::__float_to_tf32(af[i].x[t]);
            }
#pragma unroll
            for (int j = 0; j < 2; j++) {
                wmma::load_matrix_sync(bf[j], &Bs[(wn + j * 16) * AP + kk], AP);
#pragma unroll
                for (int t = 0; t < bf[j].num_elements; t++)
                    bf[j].x[t] = wmma::__float_to_tf32(bf[j].x[t]);
            }
#pragma unroll
            for (int i = 0; i < 4; i++)
#pragma unroll
                for (int j = 0; j < 2; j++)
                    wmma::mma_sync(cf[i][j], af[i], bf[j], cf[i][j]);
        }
        __syncthreads();
    }

#pragma unroll
    for (int i = 0; i < 4; i++)
#pragma unroll
        for (int j = 0; j < 2; j++) {
            float* dst = &g_xproj[(size_t)(m0 + wm + i * 16) * 512 + n0 + wn + j * 16];
            wmma::store_matrix_sync(dst, cf[i][j], 512, wmma::mem_row_major);
        }
}

// ---------------------------------------------------------------------------
// Kernel 2: persistent LSTM recurrence, k-pair-packed fp32x2 (no dup movs).
// 128 CTAs x 512 threads, 2 batches/CTA.
// Thread t: kh = t>>8 (k-half), tt = t&255, gates ga=tt, gb=tt+256.
// Per (gate, half): 24 k from shared (natural pairs), 40 k in registers
// (native u64 pairs). 4 accumulators {ga,gb}x{b0,b1}, packed over even/odd k,
// horizontal-added, combined via partial buffer in smem.
// ---------------------------------------------------------------------------
#define SH_CH 6    // shared 4-k chunks per half (24 k)
#define RG_CH 10   // register 4-k chunks per half (40 k)
#define RG_PAIRS 20

typedef unsigned long long u64;

__device__ __forceinline__ void fma2(u64& d, u64 a, u64 b) {
    asm("fma.rn.f32x2 %0, %1, %2, %0;" : "+l"(d) : "l"(a), "l"(b));
}
__device__ __forceinline__ float hsum2(u64 v) {
    float lo, hi;
    asm("mov.b64 {%0, %1}, %2;" : "=f"(lo), "=f"(hi) : "l"(v));
    return lo + hi;
}
__device__ __forceinline__ float fast_sigmoid(float x) {
    return __fdividef(1.f, 1.f + __expf(-x));
}
__device__ __forceinline__ float fast_tanh(float x) {
    float e = __expf(2.f * x);
    return 1.f - __fdividef(2.f, e + 1.f);
}

// smem layout (floats):
//   Wsh   : [2][SH_CH][512] float4   -> 2*6*512*4 = 24576 floats
//   hshf  : [2][128]                 -> 256 floats   (offset 24576)
//   partf : [2][512][2]              -> 2048 floats  (offset 24832)
#define SMEM_W_F4   (2 * SH_CH * 512)
#define SMEM_H_OFF  (SMEM_W_F4 * 4)
#define SMEM_P_OFF  (SMEM_H_OFF + 256)
#define SMEM_FLOATS (SMEM_P_OFF + 2048)

__global__ __launch_bounds__(512, 1)
void lstm_rec(const float* __restrict__ Whh,
              const float* __restrict__ h0,
              const float* __restrict__ c0,
              float* __restrict__ out)
{
    extern __shared__ float smem[];
    float* hshf  = smem + SMEM_H_OFF;
    float* partf = smem + SMEM_P_OFF;

    const int t   = threadIdx.x;
    const int blk = blockIdx.x;
    const int kh  = t >> 8;        // 0 or 1
    const int tt  = t & 255;
    const int ga  = tt;
    const int gb  = tt + 256;
    const int kbase = kh * 64;

    // --- cooperative load of shared weight chunks ---
    // smem float i = ((kc)*512 + g)*4 + j  <->  Whh[g*128 + (kc>=SH_CH? 64:0) + (kc%SH_CH)*4 + j]
    for (int i = t; i < SMEM_W_F4 * 4; i += 512) {
        int j  = i & 3;
        int g  = (i >> 2) & 511;
        int kc = i >> 11;                 // 0..11 = kh*SH_CH + c
        int khh = kc / SH_CH, c = kc % SH_CH;
        smem[i] = Whh[g * 128 + khh * 64 + c * 4 + j];
    }

    // --- register weights: k in [kbase+24, kbase+64) as native u64 pairs ---
    u64 wA[RG_PAIRS], wB[RG_PAIRS];
    {
        const u64* pa = reinterpret_cast<const u64*>(Whh + ga * 128 + kbase + SH_CH * 4);
        const u64* pb = reinterpret_cast<const u64*>(Whh + gb * 128 + kbase + SH_CH * 4);
#pragma unroll
        for (int i = 0; i < RG_PAIRS; i++) { wA[i] = pa[i]; wB[i] = pb[i]; }
    }

    // --- state init (t<256 threads own (b,e)) ---
    const int b  = tt >> 7;
    const int e  = tt & 127;
    const int bg = blk * 2 + b;
    float creg = 0.f;
    if (kh == 0) {
        hshf[b * 128 + e] = h0[bg * 128 + e];
        creg = c0[bg * 128 + e];
    }
    __syncthreads();

    const float* xp0 = g_xproj + (size_t)(blk * 2) * 512;       // batch0
    const float* xp1 = g_xproj + (size_t)(blk * 2 + 1) * 512;   // batch1
    float* outp = out + (size_t)bg * E_DIM + e;                  // for both kh roles

    const ulonglong2* Wsh2 = reinterpret_cast<const ulonglong2*>(smem);
    const ulonglong2* Hb0  = reinterpret_cast<const ulonglong2*>(hshf + kbase);
    const ulonglong2* Hb1  = reinterpret_cast<const ulonglong2*>(hshf + 128 + kbase);

    // xp prefetch (kh==0 threads only)
    float xA0 = 0.f, xA1 = 0.f, xB0 = 0.f, xB1 = 0.f;
    if (kh == 0) {
        xA0 = xp0[ga]; xA1 = xp1[ga];
        xB0 = xp0[gb]; xB1 = xp1[gb];
    }

    float* pA = partf + (kh * 512 + ga) * 2;
    float* pB = partf + (kh * 512 + gb) * 2;

    for (int step = 0; step < T_STEPS; step++) {
        // deferred softplus + output store for previous step (kh==1 warps),
        // overlapped with this step's FMA phase. hshf holds h_{step-1} here.
        if (kh == 1 && step > 0) {
            float h = hshf[b * 128 + e];
            outp[(size_t)(step - 1) * (BATCH * E_DIM)] = log1pf(__expf(h));
        }

        // prefetch next xp (kh==0)
        float nA0 = 0.f, nA1 = 0.f, nB0 = 0.f, nB1 = 0.f;
        if (kh == 0) {
            int ns = (step + 1 < T_STEPS) ? step + 1 : step;
            size_t soff = (size_t)ns * (BATCH * G4);
            nA0 = __ldg(&xp0[soff + ga]); nA1 = __ldg(&xp1[soff + ga]);
            nB0 = __ldg(&xp0[soff + gb]); nB1 = __ldg(&xp1[soff + gb]);
        }

        u64 aA0 = 0, aA1 = 0, aB0 = 0, aB1 = 0;

        // shared-weight chunks (k = kbase .. kbase+23)
#pragma unroll
        for (int c = 0; c < SH_CH; c++) {
            ulonglong2 wa = Wsh2[(kh * SH_CH + c) * 512 + ga];
            ulonglong2 wb = Wsh2[(kh * SH_CH + c) * 512 + gb];
            ulonglong2 h0c = Hb0[c];
            ulonglong2 h1c = Hb1[c];
            fma2(aA0, wa.x, h0c.x); fma2(aA0, wa.y, h0c.y);
            fma2(aA1, wa.x, h1c.x); fma2(aA1, wa.y, h1c.y);
            fma2(aB0, wb.x, h0c.x); fma2(aB0, wb.y, h0c.y);
            fma2(aB1, wb.x, h1c.x); fma2(aB1, wb.y, h1c.y);
        }
        // register-weight chunks (k = kbase+24 .. kbase+63)
#pragma unroll
        for (int c = 0; c < RG_CH; c++) {
            ulonglong2 h0c = Hb0[SH_CH + c];
            ulonglong2 h1c = Hb1[SH_CH + c];
            u64 wa0 = wA[2 * c], wa1 = wA[2 * c + 1];
            u64 wb0 = wB[2 * c], wb1 = wB[2 * c + 1];
            fma2(aA0, wa0, h0c.x); fma2(aA0, wa1, h0c.y);
            fma2(aA1, wa0, h1c.x); fma2(aA1, wa1, h1c.y);
            fma2(aB0, wb0, h0c.x); fma2(aB0, wb1, h0c.y);
            fma2(aB1, wb0, h1c.x); fma2(aB1, wb1, h1c.y);
        }

        // horizontal sums + xp add (kh==0 carries the xp term)
        float sA0 = hsum2(aA0) + xA0;
        float sA1 = hsum2(aA1) + xA1;
        float sB0 = hsum2(aB0) + xB0;
        float sB1 = hsum2(aB1) + xB1;
        pA[0] = sA0; pA[1] = sA1;
        pB[0] = sB0; pB[1] = sB1;
        __syncthreads();

        // epilogue: t < 256, thread (b, e)
        if (kh == 0) {
            float gi = partf[(0   + e) * 2 + b] + partf[(512 + 0   + e) * 2 + b];
            float gf = partf[(128 + e) * 2 + b] + partf[(512 + 128 + e) * 2 + b];
            float gg = partf[(256 + e) * 2 + b] + partf[(512 + 256 + e) * 2 + b];
            float go = partf[(384 + e) * 2 + b] + partf[(512 + 384 + e) * 2 + b];
            float i_ = fast_sigmoid(gi);
            float f_ = fast_sigmoid(gf);
            float g_ = fast_tanh(gg);
            float o_ = fast_sigmoid(go);
            creg = f_ * creg + i_ * g_;
            float h = o_ * fast_tanh(creg);
            hshf[b * 128 + e] = h;
        }
        __syncthreads();

        xA0 = nA0; xA1 = nA1; xB0 = nB0; xB1 = nB1;
    }

    // final step's output (kh==1 threads)
    if (kh == 1) {
        float h = hshf[b * 128 + e];
        outp[(size_t)(T_STEPS - 1) * (BATCH * E_DIM)] = log1pf(__expf(h));
    }
}

// ---------------------------------------------------------------------------
extern "C" void kernel_launch(void* const* d_in, const int* in_sizes, int n_in,
                              void* d_out, int out_size)
{
    const float* x   = (const float*)d_in[0];
    const float* h0  = (const float*)d_in[1];
    const float* c0  = (const float*)d_in[2];
    const float* Wih = (const float*)d_in[3];
    const float* Whh = (const float*)d_in[4];
    const float* bih = (const float*)d_in[5];
    const float* bhh = (const float*)d_in[6];
    float* out = (float*)d_out;

    const int smem_bytes = SMEM_FLOATS * 4;  // 107,520 B
    cudaFuncSetAttribute((const void*)lstm_rec,
                         cudaFuncAttributeMaxDynamicSharedMemorySize, smem_bytes);

    xproj_gemm_tf32<<<dim3(4, 2048), 256>>>(x, Wih, bih, bhh);
    lstm_rec<<<128, 512, smem_bytes>>>(Whh, h0, c0, out);
}